// round 16
// baseline (speedup 1.0000x reference)
#include <cuda_runtime.h>
#include <math.h>

// ---------------------------------------------------------------------------
// PlaneElement fused, R16: single launch, z-space hot loop (2 live consts),
// smem-staged z, rolling flux window, monotone-vel reduction.
// BLOCK=256 / EPT=16 / TILE=4096 -> exactly 1024 blocks, one wave, 8 CTAs/SM.
// Per-block consts: warp 0 parallel scalar loads -> thread 0 derives -> smem.
// Output: [outflow_q, infil_rate_element, infil_depth_element, max_cfl]
// ---------------------------------------------------------------------------

#define BLOCK 256
#define EPT   16
#define TILE  (BLOCK * EPT)      // 4096
#define MAX_BLOCKS 8192
#define EPSF  1e-8f
#define FULLM 0xffffffffu

struct CC {
    float zk1, zk0;    // z = max(zk1*d + zk0, 0)
    float Ka, Kb;      // fp*dt = Ka + Kb*d
    float raindt;      // avail = raindt + d
    float l2C;         // flux = ex2(5/3 lg2 z - 2/3 lg2(1+z) + l2C)
    float dtdxz;       // z_next = z - dtdxz * dflux
    float z2A;         // A = z2A * z
    float csw, WID;    // cold paths
    float l2cman;
    float dtdx, inv_dt;
};

__device__ float        g_psum[MAX_BLOCKS];
__device__ float        g_pmax[MAX_BLOCKS];
__device__ float        g_outflow;
__device__ unsigned int g_count = 0;

__device__ __forceinline__ float fast_lg2(float x)
{ float r; asm("lg2.approx.f32 %0, %1;" : "=f"(r) : "f"(x)); return r; }
__device__ __forceinline__ float fast_ex2(float x)
{ float r; asm("ex2.approx.f32 %0, %1;" : "=f"(r) : "f"(x)); return r; }

// full-form manning p' (cold paths: outflow, finale)
__device__ __forceinline__ float manning_pc(float A, float csw, float WID, float l2cman)
{
    float wp = fmaf(csw, A, WID);
    float As = fmaxf(A, EPSF);
    float r  = __fdividef(As, wp);
    return fast_ex2(fmaf(0.66666667f, fast_lg2(r), l2cman));
}

// z-space minmod flux: a = z0 - z_left, b = z_right - z0
__device__ __forceinline__ float flux_z(float a, float b, float z0, float l2C)
{
    float m  = (fabsf(a) < fabsf(b)) ? a : b;
    float s  = (a * b > 0.0f) ? m : 0.0f;
    float zf = fmaf(0.5f, s, z0);
    float e  = fmaf(1.66666667f, fast_lg2(zf),
               fmaf(-0.66666667f, fast_lg2(1.0f + zf), l2C));
    return fast_ex2(e);
}

__global__ void __launch_bounds__(BLOCK, 8)
fused_kernel(const float* __restrict__ depth, int N, int nblocks,
             float* __restrict__ out,
             const float* rain_rate, const float* dt,
             const float* theta_current, const float* F_cumulative,
             const float* WID_p, const float* SS1, const float* SS2,
             const float* MAN, const float* SL, const float* dx,
             const float* Ks, const float* psi, const float* theta_s)
{
    __shared__ __align__(16) float sZ[TILE + 8];
    __shared__ float sv[13];
    __shared__ CC    sc;
    __shared__ float w0[BLOCK / 32], w1[BLOCK / 32];
    __shared__ int   s_last;

    const int tid  = threadIdx.x;
    const int lane = tid & 31;
    const int base = blockIdx.x * TILE;

    // ---- per-block constants: warp 0 parallel scalar loads ----
    if (tid < 32) {
        if      (tid == 0)  sv[0]  = __ldg(rain_rate);
        else if (tid == 1)  sv[1]  = __ldg(dt);
        else if (tid == 2)  sv[2]  = __ldg(theta_current);
        else if (tid == 3)  sv[3]  = __ldg(F_cumulative);
        else if (tid == 4)  sv[4]  = __ldg(WID_p);
        else if (tid == 5)  sv[5]  = __ldg(SS1);
        else if (tid == 6)  sv[6]  = __ldg(SS2);
        else if (tid == 7)  sv[7]  = __ldg(MAN);
        else if (tid == 8)  sv[8]  = __ldg(SL);
        else if (tid == 9)  sv[9]  = __ldg(dx);
        else if (tid == 10) sv[10] = __ldg(Ks);
        else if (tid == 11) sv[11] = __ldg(psi);
        else if (tid == 12) sv[12] = __ldg(theta_s);
        __syncwarp();
        if (tid == 0) {
            float rr = sv[0], dtv = sv[1], th = sv[2], F = sv[3], wid = sv[4];
            float ss1 = sv[5], ss2 = sv[6], man = sv[7], sl = sv[8], dxv = sv[9];
            float ks = sv[10], ps = sv[11], ths = sv[12];
            float dtheta = fmaxf(ths - th, 0.0f);
            float F_safe = fmaxf(F, 1e-6f);
            float ksdt   = ks * dtv;
            float Kb     = ksdt / F_safe;
            float Ka     = ksdt + Kb * (ps * dtheta);
            float raindt = rr * dtv;
            float css    = sqrtf(1.0f + ss1 * ss1) + sqrtf(1.0f + ss2 * ss2);
            float csw    = css / wid;
            float cman   = sqrtf(sl) / man;
            float l2cman = log2f(cman);
            float zscale = csw / wid;
            sc.zk1    = (1.0f - Kb) * wid * zscale;
            sc.zk0    = (raindt - Ka) * wid * zscale;
            sc.Kb     = Kb;
            sc.Ka     = Ka;
            sc.raindt = raindt;
            sc.l2C    = l2cman + log2f(wid) - 1.66666667f * log2f(csw);
            sc.dtdxz  = (dtv / dxv) * zscale;
            sc.z2A    = 1.0f / zscale;
            sc.csw    = csw;
            sc.WID    = wid;
            sc.l2cman = l2cman;
            sc.dtdx   = dtv / dxv;
            sc.inv_dt = 1.0f / dtv;
        }
    }
    __syncthreads();

    const bool interior = (base >= 2) && (base + TILE + 2 <= N);

    float local_sum  = 0.0f;
    float local_maxZ = 0.0f;

    if (interior) {
        // ---- stage z into smem (coalesced float4), infil sum ----
        {
            const float zk1 = sc.zk1, zk0 = sc.zk0;
            const float Kb = sc.Kb, Ka = sc.Ka, raindt = sc.raindt;
            const float4* dp = (const float4*)(depth + base);
            float4* sZ4 = (float4*)(sZ + 4);
            #pragma unroll 1
            for (int idx = tid; idx < TILE / 4; idx += BLOCK) {
                float4 d4 = __ldg(dp + idx);
                float4 z4;
                z4.x = fmaxf(fmaf(zk1, d4.x, zk0), 0.0f);
                z4.y = fmaxf(fmaf(zk1, d4.y, zk0), 0.0f);
                z4.z = fmaxf(fmaf(zk1, d4.z, zk0), 0.0f);
                z4.w = fmaxf(fmaf(zk1, d4.w, zk0), 0.0f);
                local_sum += (fminf(fmaf(Kb, d4.x, Ka), raindt + d4.x)
                            + fminf(fmaf(Kb, d4.y, Ka), raindt + d4.y))
                           + (fminf(fmaf(Kb, d4.z, Ka), raindt + d4.z)
                            + fminf(fmaf(Kb, d4.w, Ka), raindt + d4.w));
                sZ4[idx] = z4;
            }
            if (tid < 3) {
                int g = (tid < 2) ? (base - 2 + tid) : (base + TILE);
                sZ[g - base + 4] = fmaxf(fmaf(zk1, __ldg(depth + g), zk0), 0.0f);
            }
        }
        __syncthreads();

        // ---- rolling window, carried diff; reduce max z_next only ----
        const float l2C = sc.l2C, dtdxz = sc.dtdxz;
        const int s0 = tid * EPT + 2;          // sZ[s0] = z(t0-2)
        float Zcur = sZ[s0 + 1];
        float Znxt = sZ[s0 + 2];
        float a = Zcur - sZ[s0];
        float b = Znxt - Zcur;
        float flux_prev = flux_z(a, b, Zcur, l2C);   // node t0-1
        #pragma unroll
        for (int i = 0; i < EPT; i++) {
            Zcur = Znxt;
            Znxt = sZ[s0 + 3 + i];
            a = b;
            b = Znxt - Zcur;
            float fluxj  = flux_z(a, b, Zcur, l2C);
            float Z_next = fmaxf(fmaf(-dtdxz, fluxj - flux_prev, Zcur), 0.0f);
            local_maxZ   = fmaxf(local_maxZ, Z_next);
            flux_prev    = fluxj;
        }
    } else {
        // ---- edge blocks (2): guarded staging + guarded window ----
        const float zk1 = sc.zk1, zk0 = sc.zk0;
        const float Kb = sc.Kb, Ka = sc.Ka, raindt = sc.raindt;
        const float csw = sc.csw, WID = sc.WID, l2cman = sc.l2cman;
        const float dtdxz = sc.dtdxz, z2A = sc.z2A, l2C = sc.l2C;

        #pragma unroll 1
        for (int k = tid; k < TILE + 3; k += BLOCK) {
            int g = base - 2 + k;
            float Zval = 0.0f;
            if (g >= 0 && g < N) {
                float d = depth[g];
                Zval = fmaxf(fmaf(zk1, d, zk0), 0.0f);
                if (g >= base) local_sum += fminf(fmaf(Kb, d, Ka), raindt + d);
            }
            sZ[k + 2] = Zval;
        }
        __syncthreads();

        const int t0 = base + tid * EPT;
        float flux_prev = 0.0f;
        {
            int j = t0 - 1;
            if (j >= 0 && j < N) {
                int sj = j - base + 4;
                float Z = sZ[sj];
                float slope = 0.0f;
                if (j > 0 && j < N - 1) {
                    float a = Z - sZ[sj - 1];
                    float b = sZ[sj + 1] - Z;
                    float m = (fabsf(a) < fabsf(b)) ? a : b;
                    slope   = (a * b > 0.0f) ? m : 0.0f;
                }
                flux_prev = flux_z(slope, slope, Z, l2C);
            }
        }
        #pragma unroll 1
        for (int i = 0; i < EPT; i++) {
            int g = t0 + i;
            if (g >= N) break;
            int sg = g - base + 4;
            float Z = sZ[sg];
            float slope = 0.0f;
            if (g > 0 && g < N - 1) {
                float a = Z - sZ[sg - 1];
                float b = sZ[sg + 1] - Z;
                float m = (fabsf(a) < fabsf(b)) ? a : b;
                slope   = (a * b > 0.0f) ? m : 0.0f;
            }
            float fluxj = flux_z(slope, slope, Z, l2C);
            float flux_in = (g == 0) ? 0.0f : flux_prev;
            float Z_next  = fmaxf(fmaf(-dtdxz, fluxj - flux_in, Z), 0.0f);
            local_maxZ    = fmaxf(local_maxZ, Z_next);
            if (g == N - 1) {
                float A_next = z2A * Z_next;
                g_outflow = A_next * manning_pc(A_next, csw, WID, l2cman);
            }
            flux_prev = fluxj;
        }
    }

    // ---- deterministic block reduction ----
    #pragma unroll
    for (int o = 16; o > 0; o >>= 1) {
        local_sum  += __shfl_down_sync(FULLM, local_sum, o);
        local_maxZ  = fmaxf(local_maxZ, __shfl_down_sync(FULLM, local_maxZ, o));
    }
    int warp = tid >> 5;
    if (lane == 0) { w0[warp] = local_sum; w1[warp] = local_maxZ; }
    __syncthreads();
    if (tid == 0) {
        float s = 0.0f, m = 0.0f;
        #pragma unroll
        for (int w = 0; w < BLOCK / 32; w++) {
            s += w0[w];
            m  = fmaxf(m, w1[w]);
        }
        g_psum[blockIdx.x] = s;
        g_pmax[blockIdx.x] = m;
        __threadfence();
        unsigned int ticket = atomicAdd(&g_count, 1u);
        s_last = (ticket == (unsigned int)(nblocks - 1)) ? 1 : 0;
    }
    __syncthreads();

    // ---- last block: fixed-order grid reduction, single vel eval ----
    if (s_last) {
        __threadfence();
        float s = 0.0f, m = 0.0f;
        for (int i = tid; i < nblocks; i += BLOCK) {
            s += g_psum[i];
            m  = fmaxf(m, g_pmax[i]);
        }
        #pragma unroll
        for (int o = 16; o > 0; o >>= 1) {
            s += __shfl_down_sync(FULLM, s, o);
            m  = fmaxf(m, __shfl_down_sync(FULLM, m, o));
        }
        if (lane == 0) { w0[warp] = s; w1[warp] = m; }
        __syncthreads();
        if (tid == 0) {
            float st = 0.0f, mZ = 0.0f;
            #pragma unroll
            for (int w = 0; w < BLOCK / 32; w++) {
                st += w0[w];
                mZ  = fmaxf(mZ, w1[w]);
            }
            float mA  = sc.z2A * mZ;
            float vel = manning_pc(mA, sc.csw, sc.WID, sc.l2cman)
                      * fminf(mA * 1e8f, 1.0f);
            float mean_depth = st / (float)N;
            out[0] = g_outflow;
            out[1] = mean_depth * sc.inv_dt;
            out[2] = mean_depth;
            out[3] = vel * sc.dtdx;
            g_count = 0;   // reset for next graph replay
        }
    }
}

// ---------------------------------------------------------------------------
extern "C" void kernel_launch(void* const* d_in, const int* in_sizes, int n_in,
                              void* d_out, int out_size)
{
    const float* depth = (const float*)d_in[0];
    const int N = in_sizes[0];
    int nblocks = (N + TILE - 1) / TILE;   // N=2^22 -> 1024 blocks (one wave)
    if (nblocks > MAX_BLOCKS) nblocks = MAX_BLOCKS;

    fused_kernel<<<nblocks, BLOCK>>>(
        depth, N, nblocks, (float*)d_out,
        (const float*)d_in[1],  (const float*)d_in[2],  (const float*)d_in[4],
        (const float*)d_in[5],  (const float*)d_in[6],  (const float*)d_in[7],
        (const float*)d_in[8],  (const float*)d_in[9],  (const float*)d_in[10],
        (const float*)d_in[11], (const float*)d_in[12], (const float*)d_in[13],
        (const float*)d_in[14]);
}

// round 17
// speedup vs baseline: 1.1216x; 1.1216x over previous
#include <cuda_runtime.h>
#include <math.h>

// ---------------------------------------------------------------------------
// PlaneElement fused, R17: single launch, z-space hot loop, smem-staged z,
// rolling flux window, monotone-vel reduction. EPT=15 (odd stride ->
// gcd(15,32)=1 -> CONFLICT-FREE strided LDS in the window loop; EPT=14 had
// 2-way and EPT=16 had 16-way conflicts). TILE=3840 -> 1093 blocks, one wave.
// Output: [outflow_q, infil_rate_element, infil_depth_element, max_cfl]
// ---------------------------------------------------------------------------

#define BLOCK 256
#define EPT   15
#define TILE  (BLOCK * EPT)      // 3840
#define MAX_BLOCKS 8192
#define EPSF  1e-8f
#define FULLM 0xffffffffu

struct CC {
    float zk1, zk0;    // z = max(zk1*d + zk0, 0)
    float Ka, Kb;      // fp*dt = Ka + Kb*d
    float raindt;      // avail = raindt + d
    float l2C;         // flux = ex2(5/3 lg2 z - 2/3 lg2(1+z) + l2C)
    float dtdxz;       // z_next = z - dtdxz * dflux
    float z2A;         // A = z2A * z
    float csw, WID;    // cold paths
    float l2cman;
    float dtdx, inv_dt;
};

__device__ float        g_psum[MAX_BLOCKS];
__device__ float        g_pmax[MAX_BLOCKS];
__device__ float        g_outflow;
__device__ unsigned int g_count = 0;

__device__ __forceinline__ float fast_lg2(float x)
{ float r; asm("lg2.approx.f32 %0, %1;" : "=f"(r) : "f"(x)); return r; }
__device__ __forceinline__ float fast_ex2(float x)
{ float r; asm("ex2.approx.f32 %0, %1;" : "=f"(r) : "f"(x)); return r; }

// full-form manning p' (cold paths: outflow, finale)
__device__ __forceinline__ float manning_pc(float A, float csw, float WID, float l2cman)
{
    float wp = fmaf(csw, A, WID);
    float As = fmaxf(A, EPSF);
    float r  = __fdividef(As, wp);
    return fast_ex2(fmaf(0.66666667f, fast_lg2(r), l2cman));
}

// z-space minmod flux: a = z0 - z_left, b = z_right - z0
__device__ __forceinline__ float flux_z(float a, float b, float z0, float l2C)
{
    float m  = (fabsf(a) < fabsf(b)) ? a : b;
    float s  = (a * b > 0.0f) ? m : 0.0f;
    float zf = fmaf(0.5f, s, z0);
    float e  = fmaf(1.66666667f, fast_lg2(zf),
               fmaf(-0.66666667f, fast_lg2(1.0f + zf), l2C));
    return fast_ex2(e);
}

__global__ void __launch_bounds__(BLOCK, 8)
fused_kernel(const float* __restrict__ depth, int N, int nblocks,
             float* __restrict__ out,
             const float* rain_rate, const float* dt,
             const float* theta_current, const float* F_cumulative,
             const float* WID_p, const float* SS1, const float* SS2,
             const float* MAN, const float* SL, const float* dx,
             const float* Ks, const float* psi, const float* theta_s)
{
    __shared__ __align__(16) float sZ[TILE + 8];
    __shared__ float sv[13];
    __shared__ CC    sc;
    __shared__ float w0[BLOCK / 32], w1[BLOCK / 32];
    __shared__ int   s_last;

    const int tid  = threadIdx.x;
    const int lane = tid & 31;
    const int base = blockIdx.x * TILE;

    // ---- per-block constants: warp 0 parallel scalar loads ----
    if (tid < 32) {
        if      (tid == 0)  sv[0]  = __ldg(rain_rate);
        else if (tid == 1)  sv[1]  = __ldg(dt);
        else if (tid == 2)  sv[2]  = __ldg(theta_current);
        else if (tid == 3)  sv[3]  = __ldg(F_cumulative);
        else if (tid == 4)  sv[4]  = __ldg(WID_p);
        else if (tid == 5)  sv[5]  = __ldg(SS1);
        else if (tid == 6)  sv[6]  = __ldg(SS2);
        else if (tid == 7)  sv[7]  = __ldg(MAN);
        else if (tid == 8)  sv[8]  = __ldg(SL);
        else if (tid == 9)  sv[9]  = __ldg(dx);
        else if (tid == 10) sv[10] = __ldg(Ks);
        else if (tid == 11) sv[11] = __ldg(psi);
        else if (tid == 12) sv[12] = __ldg(theta_s);
        __syncwarp();
        if (tid == 0) {
            float rr = sv[0], dtv = sv[1], th = sv[2], F = sv[3], wid = sv[4];
            float ss1 = sv[5], ss2 = sv[6], man = sv[7], sl = sv[8], dxv = sv[9];
            float ks = sv[10], ps = sv[11], ths = sv[12];
            float dtheta = fmaxf(ths - th, 0.0f);
            float F_safe = fmaxf(F, 1e-6f);
            float ksdt   = ks * dtv;
            float Kb     = ksdt / F_safe;
            float Ka     = ksdt + Kb * (ps * dtheta);
            float raindt = rr * dtv;
            float css    = sqrtf(1.0f + ss1 * ss1) + sqrtf(1.0f + ss2 * ss2);
            float csw    = css / wid;
            float cman   = sqrtf(sl) / man;
            float l2cman = log2f(cman);
            float zscale = csw / wid;
            sc.zk1    = (1.0f - Kb) * wid * zscale;
            sc.zk0    = (raindt - Ka) * wid * zscale;
            sc.Kb     = Kb;
            sc.Ka     = Ka;
            sc.raindt = raindt;
            sc.l2C    = l2cman + log2f(wid) - 1.66666667f * log2f(csw);
            sc.dtdxz  = (dtv / dxv) * zscale;
            sc.z2A    = 1.0f / zscale;
            sc.csw    = csw;
            sc.WID    = wid;
            sc.l2cman = l2cman;
            sc.dtdx   = dtv / dxv;
            sc.inv_dt = 1.0f / dtv;
        }
    }
    __syncthreads();

    const bool interior = (base >= 2) && (base + TILE + 2 <= N);

    float local_sum  = 0.0f;
    float local_maxZ = 0.0f;

    if (interior) {
        // ---- stage z into smem (coalesced float4), infil sum ----
        {
            const float zk1 = sc.zk1, zk0 = sc.zk0;
            const float Kb = sc.Kb, Ka = sc.Ka, raindt = sc.raindt;
            const float4* dp = (const float4*)(depth + base);
            float4* sZ4 = (float4*)(sZ + 4);
            #pragma unroll 1
            for (int idx = tid; idx < TILE / 4; idx += BLOCK) {
                float4 d4 = __ldg(dp + idx);
                float4 z4;
                z4.x = fmaxf(fmaf(zk1, d4.x, zk0), 0.0f);
                z4.y = fmaxf(fmaf(zk1, d4.y, zk0), 0.0f);
                z4.z = fmaxf(fmaf(zk1, d4.z, zk0), 0.0f);
                z4.w = fmaxf(fmaf(zk1, d4.w, zk0), 0.0f);
                local_sum += (fminf(fmaf(Kb, d4.x, Ka), raindt + d4.x)
                            + fminf(fmaf(Kb, d4.y, Ka), raindt + d4.y))
                           + (fminf(fmaf(Kb, d4.z, Ka), raindt + d4.z)
                            + fminf(fmaf(Kb, d4.w, Ka), raindt + d4.w));
                sZ4[idx] = z4;
            }
            if (tid < 3) {
                int g = (tid < 2) ? (base - 2 + tid) : (base + TILE);
                sZ[g - base + 4] = fmaxf(fmaf(zk1, __ldg(depth + g), zk0), 0.0f);
            }
        }
        __syncthreads();

        // ---- rolling window, carried diff; conflict-free strided LDS ----
        const float l2C = sc.l2C, dtdxz = sc.dtdxz;
        const int s0 = tid * EPT + 2;          // sZ[s0] = z(t0-2); stride 15
        float Zcur = sZ[s0 + 1];
        float Znxt = sZ[s0 + 2];
        float a = Zcur - sZ[s0];
        float b = Znxt - Zcur;
        float flux_prev = flux_z(a, b, Zcur, l2C);   // node t0-1
        #pragma unroll
        for (int i = 0; i < EPT; i++) {
            Zcur = Znxt;
            Znxt = sZ[s0 + 3 + i];
            a = b;
            b = Znxt - Zcur;
            float fluxj  = flux_z(a, b, Zcur, l2C);
            float Z_next = fmaxf(fmaf(-dtdxz, fluxj - flux_prev, Zcur), 0.0f);
            local_maxZ   = fmaxf(local_maxZ, Z_next);
            flux_prev    = fluxj;
        }
    } else {
        // ---- edge blocks (2): guarded staging + guarded window ----
        const float zk1 = sc.zk1, zk0 = sc.zk0;
        const float Kb = sc.Kb, Ka = sc.Ka, raindt = sc.raindt;
        const float csw = sc.csw, WID = sc.WID, l2cman = sc.l2cman;
        const float dtdxz = sc.dtdxz, z2A = sc.z2A, l2C = sc.l2C;

        #pragma unroll 1
        for (int k = tid; k < TILE + 3; k += BLOCK) {
            int g = base - 2 + k;
            float Zval = 0.0f;
            if (g >= 0 && g < N) {
                float d = depth[g];
                Zval = fmaxf(fmaf(zk1, d, zk0), 0.0f);
                if (g >= base) local_sum += fminf(fmaf(Kb, d, Ka), raindt + d);
            }
            sZ[k + 2] = Zval;
        }
        __syncthreads();

        const int t0 = base + tid * EPT;
        float flux_prev = 0.0f;
        {
            int j = t0 - 1;
            if (j >= 0 && j < N) {
                int sj = j - base + 4;
                float Z = sZ[sj];
                float slope = 0.0f;
                if (j > 0 && j < N - 1) {
                    float a = Z - sZ[sj - 1];
                    float b = sZ[sj + 1] - Z;
                    float m = (fabsf(a) < fabsf(b)) ? a : b;
                    slope   = (a * b > 0.0f) ? m : 0.0f;
                }
                flux_prev = flux_z(slope, slope, Z, l2C);
            }
        }
        #pragma unroll 1
        for (int i = 0; i < EPT; i++) {
            int g = t0 + i;
            if (g >= N) break;
            int sg = g - base + 4;
            float Z = sZ[sg];
            float slope = 0.0f;
            if (g > 0 && g < N - 1) {
                float a = Z - sZ[sg - 1];
                float b = sZ[sg + 1] - Z;
                float m = (fabsf(a) < fabsf(b)) ? a : b;
                slope   = (a * b > 0.0f) ? m : 0.0f;
            }
            float fluxj = flux_z(slope, slope, Z, l2C);
            float flux_in = (g == 0) ? 0.0f : flux_prev;
            float Z_next  = fmaxf(fmaf(-dtdxz, fluxj - flux_in, Z), 0.0f);
            local_maxZ    = fmaxf(local_maxZ, Z_next);
            if (g == N - 1) {
                float A_next = z2A * Z_next;
                g_outflow = A_next * manning_pc(A_next, csw, WID, l2cman);
            }
            flux_prev = fluxj;
        }
    }

    // ---- deterministic block reduction ----
    #pragma unroll
    for (int o = 16; o > 0; o >>= 1) {
        local_sum  += __shfl_down_sync(FULLM, local_sum, o);
        local_maxZ  = fmaxf(local_maxZ, __shfl_down_sync(FULLM, local_maxZ, o));
    }
    int warp = tid >> 5;
    if (lane == 0) { w0[warp] = local_sum; w1[warp] = local_maxZ; }
    __syncthreads();
    if (tid == 0) {
        float s = 0.0f, m = 0.0f;
        #pragma unroll
        for (int w = 0; w < BLOCK / 32; w++) {
            s += w0[w];
            m  = fmaxf(m, w1[w]);
        }
        g_psum[blockIdx.x] = s;
        g_pmax[blockIdx.x] = m;
        __threadfence();
        unsigned int ticket = atomicAdd(&g_count, 1u);
        s_last = (ticket == (unsigned int)(nblocks - 1)) ? 1 : 0;
    }
    __syncthreads();

    // ---- last block: fixed-order grid reduction, single vel eval ----
    if (s_last) {
        __threadfence();
        float s = 0.0f, m = 0.0f;
        for (int i = tid; i < nblocks; i += BLOCK) {
            s += g_psum[i];
            m  = fmaxf(m, g_pmax[i]);
        }
        #pragma unroll
        for (int o = 16; o > 0; o >>= 1) {
            s += __shfl_down_sync(FULLM, s, o);
            m  = fmaxf(m, __shfl_down_sync(FULLM, m, o));
        }
        if (lane == 0) { w0[warp] = s; w1[warp] = m; }
        __syncthreads();
        if (tid == 0) {
            float st = 0.0f, mZ = 0.0f;
            #pragma unroll
            for (int w = 0; w < BLOCK / 32; w++) {
                st += w0[w];
                mZ  = fmaxf(mZ, w1[w]);
            }
            float mA  = sc.z2A * mZ;
            float vel = manning_pc(mA, sc.csw, sc.WID, sc.l2cman)
                      * fminf(mA * 1e8f, 1.0f);
            float mean_depth = st / (float)N;
            out[0] = g_outflow;
            out[1] = mean_depth * sc.inv_dt;
            out[2] = mean_depth;
            out[3] = vel * sc.dtdx;
            g_count = 0;   // reset for next graph replay
        }
    }
}

// ---------------------------------------------------------------------------
extern "C" void kernel_launch(void* const* d_in, const int* in_sizes, int n_in,
                              void* d_out, int out_size)
{
    const float* depth = (const float*)d_in[0];
    const int N = in_sizes[0];
    int nblocks = (N + TILE - 1) / TILE;   // N=2^22 -> 1093 blocks (one wave)
    if (nblocks > MAX_BLOCKS) nblocks = MAX_BLOCKS;

    fused_kernel<<<nblocks, BLOCK>>>(
        depth, N, nblocks, (float*)d_out,
        (const float*)d_in[1],  (const float*)d_in[2],  (const float*)d_in[4],
        (const float*)d_in[5],  (const float*)d_in[6],  (const float*)d_in[7],
        (const float*)d_in[8],  (const float*)d_in[9],  (const float*)d_in[10],
        (const float*)d_in[11], (const float*)d_in[12], (const float*)d_in[13],
        (const float*)d_in[14]);
}